// round 14
// baseline (speedup 1.0000x reference)
#include <cuda_runtime.h>
#include <math_constants.h>

#define WML    64
#define BATCH  64
#define SENTS  40
#define DIM    512
#define NWORDS (SENTS * WML)   /* 2560 */
#define DYN_SMEM 32768         /* 4 warps x 4-slot ring x 2048B slots */

/* ------------------- scratch (static device memory; no allocs) -------- */
__device__ float g_qpart[16][BATCH * DIM];    /* [which*8+ks]; 0-7 word, 8-15 sent */
__device__ float g_scores[BATCH * NWORDS];
__device__ float g_partM[BATCH * SENTS];
__device__ float g_partL[BATCH * SENTS];
__device__ float g_partAcc[(size_t)SENTS * BATCH * DIM];  /* 5.2 MB */
__device__ float g_c[BATCH * DIM];
__device__ float g_opart[16][BATCH * DIM];    /* out-proj split-K partials */

/* ------------------- K1: q projections — 32x64 tiles, 128 thr --------- */
/* grid (8 dt, 2 which, 16 = ks*2+ms). K-slice 64, single iteration.     */
__global__ void __launch_bounds__(128)
qproj_kernel(const float* __restrict__ src,
             const float* __restrict__ Wword,
             const float* __restrict__ Wsent) {
    const float* W = blockIdx.y ? Wsent : Wword;
    const int ks = blockIdx.z >> 1, ms = blockIdx.z & 1;
    float* out = g_qpart[blockIdx.y * 8 + ks];
    const int dt = blockIdx.x * 64;
    const int kbase = ks * 64;
    const int m0 = ms * 32;

    __shared__ float As[32][65];
    __shared__ float Bs[64][65];
    const int tid = threadIdx.x;
    const int tx = tid & 15, ty = tid >> 4;   /* 16 x 8 */

    /* A: 32 rows x 16 float4 = 512 f4 */
    for (int idx = tid; idx < 512; idx += 128) {
        const int r = idx >> 4, c4 = idx & 15;
        float4 v = *(const float4*)&src[(m0 + r) * DIM + kbase + c4 * 4];
        As[r][c4 * 4 + 0] = v.x; As[r][c4 * 4 + 1] = v.y;
        As[r][c4 * 4 + 2] = v.z; As[r][c4 * 4 + 3] = v.w;
    }
    /* B: 64 rows x 16 float4 = 1024 f4 */
    for (int idx = tid; idx < 1024; idx += 128) {
        const int r = idx >> 4, c4 = idx & 15;
        float4 v = *(const float4*)&W[(dt + r) * DIM + kbase + c4 * 4];
        Bs[r][c4 * 4 + 0] = v.x; Bs[r][c4 * 4 + 1] = v.y;
        Bs[r][c4 * 4 + 2] = v.z; Bs[r][c4 * 4 + 3] = v.w;
    }
    __syncthreads();

    float acc[4][4] = {};
    #pragma unroll 8
    for (int kk = 0; kk < 64; kk++) {
        float a[4], w[4];
        #pragma unroll
        for (int i = 0; i < 4; i++) a[i] = As[ty * 4 + i][kk];
        #pragma unroll
        for (int j = 0; j < 4; j++) w[j] = Bs[tx * 4 + j][kk];
        #pragma unroll
        for (int i = 0; i < 4; i++)
            #pragma unroll
            for (int j = 0; j < 4; j++) acc[i][j] += a[i] * w[j];
    }
    #pragma unroll
    for (int i = 0; i < 4; i++)
        #pragma unroll
        for (int j = 0; j < 4; j++)
            out[(m0 + ty * 4 + i) * DIM + dt + tx * 4 + j] = acc[i][j];
}

/* ------------------- per-warp row issue (self-loaded segments) -------- */
__device__ __forceinline__ void issue_row(const float* __restrict__ rowbase,
                                          size_t wstride, unsigned sbw,
                                          int k, int r, int ln) {
    const float* src = rowbase + (size_t)r * wstride;
    const unsigned dst = sbw + (unsigned)((k & 3) * 2048);   /* 2KB slot */
    #pragma unroll
    for (int j = 0; j < 4; j++)
        asm volatile("cp.async.cg.shared.global [%0], [%1], 16;\n"
                     :: "r"(dst + (unsigned)((ln + 32 * j) * 16)),
                        "l"(src + (ln + 32 * j) * 4));
    asm volatile("cp.async.commit_group;\n");
}

/* ------------------- K2: FUSED — 4 warps, warp-private ring ----------- */
__global__ void __launch_bounds__(128, 6)
fused_kernel(const float* __restrict__ word_bank,
             const int*   __restrict__ word_lengths,
             const float* __restrict__ sent_bank,
             const float* __restrict__ static_attn) {
    extern __shared__ float buf[];    /* [4 warps][4 slots][512]; 32KB */
    __shared__ float rm[4], rl[4];

    const int s = blockIdx.x, b = blockIdx.y;
    const int tid = threadIdx.x, wp = tid >> 5, ln = tid & 31;

    const int wl = word_lengths[b * SENTS + s];
    const int nk = (wl > wp) ? ((wl - wp + 3) >> 2) : 0;

    const size_t wstride = (size_t)BATCH * SENTS * DIM;
    const float* rowbase = word_bank + ((size_t)b * SENTS + s) * (size_t)DIM;
    float* bufw = buf + wp * 2048;
    const unsigned sbw = (unsigned)__cvta_generic_to_shared(bufw);

    /* prologue: get the stream going immediately */
    if (nk > 0) issue_row(rowbase, wstride, sbw, 0, wp,     ln);
    if (nk > 1) issue_row(rowbase, wstride, sbw, 1, wp + 4, ln);
    if (nk > 2) issue_row(rowbase, wstride, sbw, 2, wp + 8, ln);

    /* q_word = sum of 8 split-K partials (L1-resident after first warp) */
    float4 q0 = {0,0,0,0}, q1 = {0,0,0,0}, q2 = {0,0,0,0}, q3 = {0,0,0,0};
    #pragma unroll
    for (int ks = 0; ks < 8; ks++) {
        const float4* qg = (const float4*)(g_qpart[ks] + b * DIM);
        float4 t;
        t = qg[ln];      q0.x += t.x; q0.y += t.y; q0.z += t.z; q0.w += t.w;
        t = qg[ln + 32]; q1.x += t.x; q1.y += t.y; q1.z += t.z; q1.w += t.w;
        t = qg[ln + 64]; q2.x += t.x; q2.y += t.y; q2.z += t.z; q2.w += t.w;
        t = qg[ln + 96]; q3.x += t.x; q3.y += t.y; q3.z += t.z; q3.w += t.w;
    }

    /* inline ssa with q_sent = sum of partials 8..15 */
    float ssa;
    {
        const float4* sb = (const float4*)(sent_bank + ((size_t)s * BATCH + b) * DIM);
        float4 s0 = {0,0,0,0}, s1 = {0,0,0,0}, s2 = {0,0,0,0}, s3 = {0,0,0,0};
        #pragma unroll
        for (int ks = 8; ks < 16; ks++) {
            const float4* qg = (const float4*)(g_qpart[ks] + b * DIM);
            float4 t;
            t = qg[ln];      s0.x += t.x; s0.y += t.y; s0.z += t.z; s0.w += t.w;
            t = qg[ln + 32]; s1.x += t.x; s1.y += t.y; s1.z += t.z; s1.w += t.w;
            t = qg[ln + 64]; s2.x += t.x; s2.y += t.y; s2.z += t.z; s2.w += t.w;
            t = qg[ln + 96]; s3.x += t.x; s3.y += t.y; s3.z += t.z; s3.w += t.w;
        }
        float4 v;
        float sd = 0.f;
        v = sb[ln];      sd += s0.x*v.x + s0.y*v.y + s0.z*v.z + s0.w*v.w;
        v = sb[ln + 32]; sd += s1.x*v.x + s1.y*v.y + s1.z*v.z + s1.w*v.w;
        v = sb[ln + 64]; sd += s2.x*v.x + s2.y*v.y + s2.z*v.z + s2.w*v.w;
        v = sb[ln + 96]; sd += s3.x*v.x + s3.y*v.y + s3.z*v.z + s3.w*v.w;
        #pragma unroll
        for (int off = 16; off > 0; off >>= 1)
            sd += __shfl_xor_sync(0xffffffffu, sd, off);
        ssa = sd * static_attn[b * SENTS + s];
    }

    float m = -CUDART_INF_F, l = 0.f;
    float4 a0 = {0,0,0,0}, a1 = {0,0,0,0}, a2 = {0,0,0,0}, a3 = {0,0,0,0};

    for (int k = 0; k < nk; k++) {
        const int rem = nk - 1 - k;
        if (rem >= 2)      asm volatile("cp.async.wait_group 2;\n");
        else if (rem == 1) asm volatile("cp.async.wait_group 1;\n");
        else               asm volatile("cp.async.wait_group 0;\n");

        const float4* v4 = (const float4*)(bufw + (k & 3) * 512);
        float4 v0 = v4[ln], v1 = v4[ln + 32], v2 = v4[ln + 64], v3 = v4[ln + 96];
        float dot = v0.x*q0.x + v0.y*q0.y + v0.z*q0.z + v0.w*q0.w
                  + v1.x*q1.x + v1.y*q1.y + v1.z*q1.z + v1.w*q1.w
                  + v2.x*q2.x + v2.y*q2.y + v2.z*q2.z + v2.w*q2.w
                  + v3.x*q3.x + v3.y*q3.y + v3.z*q3.z + v3.w*q3.w;

        if (k + 3 < nk) issue_row(rowbase, wstride, sbw, k + 3, wp + 4 * (k + 3), ln);

        #pragma unroll
        for (int off = 16; off > 0; off >>= 1)
            dot += __shfl_xor_sync(0xffffffffu, dot, off);
        const float score = dot * ssa;
        if (ln == 0)
            g_scores[(size_t)b * NWORDS + s * WML + wp + 4 * k] = score;

        if (score > m) {           /* new max: p = 1, rescale old */
            const float scale = __expf(m - score);   /* first row: exp(-inf)=0 */
            l = l * scale + 1.f;
            a0.x = a0.x*scale + v0.x; a0.y = a0.y*scale + v0.y;
            a0.z = a0.z*scale + v0.z; a0.w = a0.w*scale + v0.w;
            a1.x = a1.x*scale + v1.x; a1.y = a1.y*scale + v1.y;
            a1.z = a1.z*scale + v1.z; a1.w = a1.w*scale + v1.w;
            a2.x = a2.x*scale + v2.x; a2.y = a2.y*scale + v2.y;
            a2.z = a2.z*scale + v2.z; a2.w = a2.w*scale + v2.w;
            a3.x = a3.x*scale + v3.x; a3.y = a3.y*scale + v3.y;
            a3.z = a3.z*scale + v3.z; a3.w = a3.w*scale + v3.w;
            m = score;
        } else {                   /* common path: no rescale */
            const float p = __expf(score - m);
            l += p;
            a0.x += p*v0.x; a0.y += p*v0.y; a0.z += p*v0.z; a0.w += p*v0.w;
            a1.x += p*v1.x; a1.y += p*v1.y; a1.z += p*v1.z; a1.w += p*v1.w;
            a2.x += p*v2.x; a2.y += p*v2.y; a2.z += p*v2.z; a2.w += p*v2.w;
            a3.x += p*v3.x; a3.y += p*v3.y; a3.z += p*v3.z; a3.w += p*v3.w;
        }
    }

    /* ---- 4-warp merge; reuse buf as racc[4][DIM] ---- */
    __syncthreads();
    float4* r4 = (float4*)(buf + wp * DIM);
    r4[ln] = a0; r4[ln + 32] = a1; r4[ln + 64] = a2; r4[ln + 96] = a3;
    if (ln == 0) { rm[wp] = m; rl[wp] = l; }
    __syncthreads();

    float mC = -CUDART_INF_F;
    #pragma unroll
    for (int i = 0; i < 4; i++) mC = fmaxf(mC, rm[i]);

    #pragma unroll
    for (int rr = 0; rr < 4; rr++) {
        const int d = tid + rr * 128;
        float sum = 0.f;
        #pragma unroll
        for (int i = 0; i < 4; i++) {
            const float sc = (rm[i] == -CUDART_INF_F) ? 0.f : __expf(rm[i] - mC);
            sum += buf[i * DIM + d] * sc;
        }
        g_partAcc[((size_t)s * BATCH + b) * DIM + d] = sum;
    }
    if (tid == 0) {
        float L = 0.f;
        #pragma unroll
        for (int i = 0; i < 4; i++) {
            const float sc = (rm[i] == -CUDART_INF_F) ? 0.f : __expf(rm[i] - mC);
            L += rl[i] * sc;
        }
        g_partM[b * SENTS + s] = mC;
        g_partL[b * SENTS + s] = L;
    }
}

/* ------------------- K3: combine partials -> c (y=0) / align (y=1) ---- */
__global__ void __launch_bounds__(512)
combine_kernel(const int* __restrict__ word_lengths,
               float* __restrict__ align_out, int has_align) {
    const int b = blockIdx.x, part = blockIdx.y, tid = threadIdx.x;
    const int wp = tid >> 5, ln = tid & 31;

    __shared__ float sScale[SENTS];
    __shared__ float sM, sinvL;

    if (wp == 0) {
        float m1 = g_partM[b * SENTS + ln];
        float m2 = (ln < SENTS - 32) ? g_partM[b * SENTS + 32 + ln] : -CUDART_INF_F;
        float mx = fmaxf(m1, m2);
        #pragma unroll
        for (int off = 16; off > 0; off >>= 1)
            mx = fmaxf(mx, __shfl_xor_sync(0xffffffffu, mx, off));
        const float sc1 = __expf(m1 - mx);
        const float sc2 = (ln < SENTS - 32) ? __expf(m2 - mx) : 0.f;
        float l = g_partL[b * SENTS + ln] * sc1;
        if (ln < SENTS - 32) l += g_partL[b * SENTS + 32 + ln] * sc2;
        #pragma unroll
        for (int off = 16; off > 0; off >>= 1)
            l += __shfl_xor_sync(0xffffffffu, l, off);
        sScale[ln] = sc1;
        if (ln < SENTS - 32) sScale[32 + ln] = sc2;
        if (ln == 0) { sM = mx; sinvL = 1.f / l; }
    }
    __syncthreads();
    const float M = sM, invL = sinvL;

    if (part == 0) {
        float csum = 0.f;
        #pragma unroll 8
        for (int s = 0; s < SENTS; s++)
            csum += sScale[s] * g_partAcc[((size_t)s * BATCH + b) * DIM + tid];
        g_c[b * DIM + tid] = csum * invL;
    } else if (has_align) {
        #pragma unroll
        for (int k = 0; k < 5; k++) {
            const int n = tid + k * 512;
            const int s = n >> 6, w = n & 63;
            float val = 1e-20f;
            if (w < word_lengths[b * SENTS + s])
                val = __expf(g_scores[(size_t)b * NWORDS + n] - M) * invL + 1e-20f;
            align_out[(size_t)b * NWORDS + n] = val;
        }
    }
}

/* ------------------- K4: out-proj — 32x64 tiles, 128 thr -------------- */
/* grid (8 dt, 16 ks, 2 ms). K-slice 64 (within g_c or src half).        */
__global__ void __launch_bounds__(128)
outproj_kernel(const float* __restrict__ src,
               const float* __restrict__ Wout) {
    const int dt = blockIdx.x * 64;
    const int ks = blockIdx.y;
    const int m0 = blockIdx.z * 32;
    const int kbase = ks * 64;
    float* out = g_opart[ks];
    const float* Abase = (ks < 8) ? (g_c + kbase) : (src + (kbase - DIM));

    __shared__ float As[32][65];
    __shared__ float Bs[64][65];
    const int tid = threadIdx.x;
    const int tx = tid & 15, ty = tid >> 4;

    for (int idx = tid; idx < 512; idx += 128) {
        const int r = idx >> 4, c4 = idx & 15;
        float4 v = *(const float4*)&Abase[(m0 + r) * DIM + c4 * 4];
        As[r][c4 * 4 + 0] = v.x; As[r][c4 * 4 + 1] = v.y;
        As[r][c4 * 4 + 2] = v.z; As[r][c4 * 4 + 3] = v.w;
    }
    for (int idx = tid; idx < 1024; idx += 128) {
        const int r = idx >> 4, c4 = idx & 15;
        float4 v = *(const float4*)&Wout[(dt + r) * (2 * DIM) + kbase + c4 * 4];
        Bs[r][c4 * 4 + 0] = v.x; Bs[r][c4 * 4 + 1] = v.y;
        Bs[r][c4 * 4 + 2] = v.z; Bs[r][c4 * 4 + 3] = v.w;
    }
    __syncthreads();

    float acc[4][4] = {};
    #pragma unroll 8
    for (int kk = 0; kk < 64; kk++) {
        float a[4], w[4];
        #pragma unroll
        for (int i = 0; i < 4; i++) a[i] = As[ty * 4 + i][kk];
        #pragma unroll
        for (int j = 0; j < 4; j++) w[j] = Bs[tx * 4 + j][kk];
        #pragma unroll
        for (int i = 0; i < 4; i++)
            #pragma unroll
            for (int j = 0; j < 4; j++) acc[i][j] += a[i] * w[j];
    }
    #pragma unroll
    for (int i = 0; i < 4; i++)
        #pragma unroll
        for (int j = 0; j < 4; j++)
            out[(m0 + ty * 4 + i) * DIM + dt + tx * 4 + j] = acc[i][j];
}

/* ------------------- K5: attn_h = tanh(sum of 16 partials) ------------- */
__global__ void __launch_bounds__(1024)
tanh_kernel(float* __restrict__ attn_out) {
    const int i = blockIdx.x * 1024 + threadIdx.x;
    float sum = 0.f;
    #pragma unroll
    for (int ks = 0; ks < 16; ks++) sum += g_opart[ks][i];
    attn_out[i] = tanhf(sum);
}

/* ------------------- launch ------------------------------------------- */
extern "C" void kernel_launch(void* const* d_in, const int* in_sizes, int n_in,
                              void* d_out, int out_size) {
    const float* source       = (const float*)d_in[0];
    const float* word_bank    = (const float*)d_in[1];
    const int*   word_lengths = (const int*)  d_in[2];
    const float* sent_bank    = (const float*)d_in[3];
    /* d_in[4] = sent_lengths: unused by forward math */
    const float* static_attn  = (const float*)d_in[5];
    const float* W_word       = (const float*)d_in[6];
    const float* W_sent       = (const float*)d_in[7];
    const float* W_out        = (const float*)d_in[8];

    float* attn_out  = (float*)d_out;
    const int need   = BATCH * DIM + BATCH * NWORDS;
    const int has_align = (out_size >= need) ? 1 : 0;
    float* align_out = attn_out + BATCH * DIM;

    cudaFuncSetAttribute(fused_kernel,
                         cudaFuncAttributeMaxDynamicSharedMemorySize, DYN_SMEM);

    qproj_kernel<<<dim3(8, 2, 16), 128>>>(source, W_word, W_sent);       /* 1 */
    fused_kernel<<<dim3(SENTS, BATCH), 128, DYN_SMEM>>>(word_bank,
                     word_lengths, sent_bank, static_attn);              /* 2 */
    combine_kernel<<<dim3(BATCH, 2), 512>>>(word_lengths, align_out,
                                            has_align);                  /* 3 */
    outproj_kernel<<<dim3(8, 16, 2), 128>>>(source, W_out);              /* 4: profiled */
    tanh_kernel<<<32, 1024>>>(attn_out);                                 /* 5 */
}